// round 14
// baseline (speedup 1.0000x reference)
#include <cuda_runtime.h>
#include <stdint.h>

#define U_NODES 100000
#define I_NODES 50000
#define N_NODES 150000
#define H 64
#define UH (U_NODES * H)       // 6,400,000
#define IH (I_NODES * H)       // 3,200,000
#define NH (N_NODES * H)       // 9,600,000
#define E_IN 2000000
#define E_DIR 4000000

#define SCAN_BLK 1024
#define N_SCAN_BLOCKS ((N_NODES + SCAN_BLK - 1) / SCAN_BLK)   // 147

// ---------------- scratch (device globals; no runtime allocation) ------------
__device__ __align__(16) float d_deg[N_NODES];
__device__ __align__(16) float d_dinv[N_NODES];
__device__ __align__(16) int   d_cnt[N_NODES];
__device__ __align__(16) int   d_rowptr[N_NODES + 1];
__device__ __align__(16) int   d_wp[N_NODES];
__device__ __align__(16) int   d_partials[N_SCAN_BLOCKS];
__device__ __align__(16) int2  d_cw[E_DIR];     // packed (col, w bits)
__device__ __align__(16) float d_e0[NH];
__device__ __align__(16) float d_e1[NH];
__device__ __align__(16) float d_acc[NH];
__device__ int d_is64;
__device__ int d_allones;

// ---------------- kernels ----------------------------------------------------

// zero node scratch; reset flags (thread 0)
__global__ void zero_kernel() {
    int i = blockIdx.x * blockDim.x + threadIdx.x;
    if (i == 0) d_allones = 1;
    if (i < N_NODES) { d_deg[i] = 0.0f; d_cnt[i] = 0; }
}

// Combined probe: block 0 detects edge-index dtype (JAX default config
// downcasts int64 -> int32, so arrays may be either); all blocks check
// whether every edge value is exactly 1.0f (full 2M-element scan).
__global__ void probe_kernel(const void* __restrict__ eu,
                             const float* __restrict__ ev) {
    int k = blockIdx.x * blockDim.x + threadIdx.x;
    if (blockIdx.x == 0) {
        __shared__ int bad;
        if (threadIdx.x == 0) bad = 0;
        __syncthreads();
        const long long* q = (const long long*)eu;
        long long v = q[threadIdx.x];
        if (v < 0 || v >= N_NODES) bad = 1;
        __syncthreads();
        if (threadIdx.x == 0) d_is64 = bad ? 0 : 1;
    }
    // all-ones check over the full value array
    bool ok = true;
    for (int t = k; t < E_IN; t += gridDim.x * blockDim.x)
        if (ev[t] != 1.0f) ok = false;
    if (!ok) d_allones = 0;
}

__device__ __forceinline__ int get_idx(const void* __restrict__ p, int k) {
    if (d_is64) return (int)((const long long*)p)[k];
    return ((const int*)p)[k];
}

// degree/count accumulation; float atomics skipped when all values are 1.0
__global__ void deg_kernel(const void* __restrict__ eu,
                           const void* __restrict__ ei,
                           const float* __restrict__ ev) {
    int k = blockIdx.x * blockDim.x + threadIdx.x;
    if (k >= E_IN) return;
    int u  = get_idx(eu, k);
    int it = get_idx(ei, k);
    if ((unsigned)u >= U_NODES || (unsigned)it >= I_NODES) return;  // safety
    it += U_NODES;
    atomicAdd(&d_cnt[u], 1);
    atomicAdd(&d_cnt[it], 1);
    if (!d_allones) {
        float v = ev[k];
        atomicAdd(&d_deg[u], v);
        atomicAdd(&d_deg[it], v);
    }
}

// block-level exclusive scan of counts (+ fused dinv computation)
__global__ void scan1_kernel() {
    __shared__ int sh[SCAN_BLK];
    int t = threadIdx.x;
    int idx = blockIdx.x * SCAN_BLK + t;
    int v = (idx < N_NODES) ? d_cnt[idx] : 0;
    // fused dinv: deg == cnt when all values are 1.0 ((float)cnt exact < 2^24)
    if (idx < N_NODES) {
        float dg = d_allones ? (float)v : d_deg[idx];
        d_dinv[idx] = (dg > 0.0f) ? rsqrtf(fmaxf(dg, 1e-12f)) : 0.0f;
    }
    sh[t] = v;
    __syncthreads();
    for (int off = 1; off < SCAN_BLK; off <<= 1) {
        int x = (t >= off) ? sh[t - off] : 0;
        __syncthreads();
        sh[t] += x;
        __syncthreads();
    }
    if (idx < N_NODES) d_rowptr[idx] = sh[t] - v;   // block-local exclusive
    if (t == SCAN_BLK - 1) d_partials[blockIdx.x] = sh[t];
}

// parallel exclusive scan of the 147 block sums (one 256-thread block)
__global__ void scan2_kernel() {
    __shared__ int sh[256];
    int t = threadIdx.x;
    int v = (t < N_SCAN_BLOCKS) ? d_partials[t] : 0;
    sh[t] = v;
    __syncthreads();
    for (int off = 1; off < 256; off <<= 1) {
        int x = (t >= off) ? sh[t - off] : 0;
        __syncthreads();
        sh[t] += x;
        __syncthreads();
    }
    if (t < N_SCAN_BLOCKS) d_partials[t] = sh[t] - v;   // exclusive
}

__global__ void scan3_kernel() {
    int idx = blockIdx.x * blockDim.x + threadIdx.x;
    if (idx < N_NODES) {
        int rp = d_rowptr[idx] + d_partials[idx >> 10];
        d_rowptr[idx] = rp;
        d_wp[idx] = rp;
    }
    if (idx == 0) d_rowptr[N_NODES] = E_DIR;
}

__global__ void scatter_kernel(const void* __restrict__ eu,
                               const void* __restrict__ ei,
                               const float* __restrict__ ev) {
    int k = blockIdx.x * blockDim.x + threadIdx.x;
    if (k >= E_IN) return;
    int u  = get_idx(eu, k);
    int it = get_idx(ei, k);
    if ((unsigned)u >= U_NODES || (unsigned)it >= I_NODES) return;  // safety
    it += U_NODES;
    float v = d_allones ? 1.0f : ev[k];
    float w = d_dinv[u] * v * d_dinv[it];   // symmetric weight
    int wb = __float_as_int(w);
    int p0 = atomicAdd(&d_wp[u], 1);
    d_cw[p0] = make_int2(it, wb);
    int p1 = atomicAdd(&d_wp[it], 1);
    d_cw[p1] = make_int2(u, wb);
}

// e0 = acc = concat(emb_users, emb_items), float4 vectorized (UH % 4 == 0)
__global__ void init_e_kernel(const float* __restrict__ emb_u,
                              const float* __restrict__ emb_i) {
    int q = blockIdx.x * blockDim.x + threadIdx.x;   // float4 index
    if (q >= NH / 4) return;
    int i = q * 4;
    float4 v = (i < UH) ? ((const float4*)emb_u)[q]
                        : ((const float4*)emb_i)[q - UH / 4];
    ((float4*)d_e0)[q]  = v;
    ((float4*)d_acc)[q] = v;
}

// ---------------- propagation layers ------------------------------------------
// Champion structure with metadata LDG reduction: one warp per row, lane l
// holds dims [2l,2l+1]. Metadata (col,w) packed as int2 and loaded TWO EDGES
// PER LDG.128 (int4, parity-aligned). Per 4 edges: 2 metadata LDGs + 4 row
// gathers = 6 LDG issues vs 12 in the scalar scheme. fp32 acc RMW in-kernel.

#define EDGE(C, WB)                                                            \
    {                                                                          \
        float w = __int_as_float(WB);                                          \
        float2 v = *(const float2*)(ein + (size_t)(C) * H + base);             \
        sum.x += w * v.x;                                                      \
        sum.y += w * v.y;                                                      \
    }

__global__ void layer_kernel(int flip) {
    const float* __restrict__ ein  = flip ? d_e1 : d_e0;
    float*       __restrict__ eout = flip ? d_e0 : d_e1;
    int warp = (blockIdx.x * blockDim.x + threadIdx.x) >> 5;
    int lane = threadIdx.x & 31;
    if (warp >= N_NODES) return;
    int s = d_rowptr[warp];
    int e = d_rowptr[warp + 1];
    float2 sum = make_float2(0.0f, 0.0f);
    int base = lane * 2;
    int j = s;
    if (j < e && (j & 1)) {               // align j to even for int4 loads
        int2 cw = d_cw[j];
        EDGE(cw.x, cw.y)
        j++;
    }
    for (; j + 3 < e; j += 4) {           // 2 x LDG.128 metadata + 4 gathers
        int4 m0 = *(const int4*)&d_cw[j];       // edges j, j+1
        int4 m1 = *(const int4*)&d_cw[j + 2];   // edges j+2, j+3
        EDGE(m0.x, m0.y) EDGE(m0.z, m0.w)
        EDGE(m1.x, m1.y) EDGE(m1.z, m1.w)
    }
    for (; j < e; j++) {
        int2 cw = d_cw[j];
        EDGE(cw.x, cw.y)
    }
    size_t o = (size_t)warp * H + base;
    *(float2*)(eout + o) = sum;
    float2* ap = (float2*)(d_acc + o);
    float2 a = *ap;
    a.x += sum.x;
    a.y += sum.y;
    *ap = a;
}

// ---------------- epilogue -----------------------------------------------------
// out = [acc_users/25 | emb_users | acc_items/25 | emb_items], float4 path.
__global__ void final_kernel(const float* __restrict__ emb_u,
                             const float* __restrict__ emb_i,
                             float* __restrict__ out, int out_n) {
    const float sc = 1.0f / 25.0f;   // alpha * 1/(L+1) = 1/5 * 1/5
    int q = blockIdx.x * blockDim.x + threadIdx.x;   // float4 index
    int i = q * 4;
    if (i >= out_n) return;
    if (i + 3 < out_n && i + 4 <= 2 * UH + 2 * IH) {
        float4 v;
        if (i < UH) {
            float4 a = ((const float4*)d_acc)[q];
            v = make_float4(a.x * sc, a.y * sc, a.z * sc, a.w * sc);
        } else if (i < 2 * UH) {
            v = ((const float4*)emb_u)[q - UH / 4];
        } else if (i < 2 * UH + IH) {
            float4 a = ((const float4*)d_acc)[UH / 4 + (q - 2 * UH / 4)];
            v = make_float4(a.x * sc, a.y * sc, a.z * sc, a.w * sc);
        } else {
            v = ((const float4*)emb_i)[q - (2 * UH + IH) / 4];
        }
        ((float4*)out)[q] = v;
    } else {
        for (int t = i; t < out_n && t < i + 4; t++) {
            float v;
            if (t < UH)                   v = d_acc[t] * sc;
            else if (t < 2 * UH)          v = emb_u[t - UH];
            else if (t < 2 * UH + IH)     v = d_acc[UH + (t - 2 * UH)] * sc;
            else if (t < 2 * UH + 2 * IH) v = emb_i[t - 2 * UH - IH];
            else                          v = 0.0f;
            out[t] = v;
        }
    }
}

// ---------------- launch ------------------------------------------------------

extern "C" void kernel_launch(void* const* d_in, const int* in_sizes, int n_in,
                              void* d_out, int out_size) {
    const float* emb_u = (const float*)d_in[0];
    const float* emb_i = (const float*)d_in[1];
    const void*  eu    = d_in[2];
    const void*  ei    = d_in[3];
    const float* ev    = (const float*)d_in[4];
    float* out = (float*)d_out;

    const int TB = 256;
    int gb_nodes = (N_NODES + TB - 1) / TB;
    int gb_edges = (E_IN + TB - 1) / TB;
    int gb_nh4   = (NH / 4 + TB - 1) / TB;
    int gb_out4  = (out_size / 4 + TB) / TB;

    zero_kernel<<<gb_nodes, TB>>>();          // also resets d_allones
    probe_kernel<<<592, TB>>>(eu, ev);        // dtype + all-ones (full scan)
    deg_kernel<<<gb_edges, TB>>>(eu, ei, ev);
    scan1_kernel<<<N_SCAN_BLOCKS, SCAN_BLK>>>();   // fused dinv
    scan2_kernel<<<1, 256>>>();
    scan3_kernel<<<gb_nodes, TB>>>();
    scatter_kernel<<<gb_edges, TB>>>(eu, ei, ev);
    init_e_kernel<<<gb_nh4, TB>>>(emb_u, emb_i);

    const int LTB = 64;                       // champion layer config
    int layer_blocks = (N_NODES * 32 + LTB - 1) / LTB;
    layer_kernel<<<layer_blocks, LTB>>>(0);   // e0 -> e1
    layer_kernel<<<layer_blocks, LTB>>>(1);   // e1 -> e0
    layer_kernel<<<layer_blocks, LTB>>>(0);   // e0 -> e1
    layer_kernel<<<layer_blocks, LTB>>>(1);   // e1 -> e0

    final_kernel<<<gb_out4, TB>>>(emb_u, emb_i, out, out_size);
}

// round 16
// speedup vs baseline: 1.0627x; 1.0627x over previous
#include <cuda_runtime.h>
#include <cuda_fp16.h>
#include <stdint.h>

#define U_NODES 100000
#define I_NODES 50000
#define N_NODES 150000
#define H 64
#define UH (U_NODES * H)       // 6,400,000
#define IH (I_NODES * H)       // 3,200,000
#define NH (N_NODES * H)       // 9,600,000
#define E_IN 2000000
#define E_DIR 4000000

#define SCAN_BLK 1024
#define N_SCAN_BLOCKS ((N_NODES + SCAN_BLK - 1) / SCAN_BLK)   // 147

// ---------------- scratch (device globals; no runtime allocation) ------------
__device__ __align__(16) float  d_deg[N_NODES];
__device__ __align__(16) float  d_dinv[N_NODES];
__device__ __align__(16) int    d_cnt[N_NODES];
__device__ __align__(16) int    d_rowptr[N_NODES + 1];
__device__ __align__(16) int    d_wp[N_NODES];
__device__ __align__(16) int    d_partials[N_SCAN_BLOCKS];
__device__ __align__(16) int    d_col[E_DIR];
__device__ __align__(16) float  d_w[E_DIR];
__device__ __align__(16) __half d_e0[NH];     // fp16 ping (gather = 4 sectors)
__device__ __align__(16) __half d_e1[NH];     // fp16 pong
__device__ __align__(16) float  d_acc[NH];    // fp32 accumulator
__device__ int d_is64;
__device__ int d_allones;

// ---------------- kernels ----------------------------------------------------

// zero node scratch; reset flags (thread 0)
__global__ void zero_kernel() {
    int i = blockIdx.x * blockDim.x + threadIdx.x;
    if (i == 0) d_allones = 1;
    if (i < N_NODES) { d_deg[i] = 0.0f; d_cnt[i] = 0; }
}

// Combined probe: block 0 detects edge-index dtype (JAX default config
// downcasts int64 -> int32, so arrays may be either); all blocks check
// whether every edge value is exactly 1.0f (full 2M-element scan).
__global__ void probe_kernel(const void* __restrict__ eu,
                             const float* __restrict__ ev) {
    int k = blockIdx.x * blockDim.x + threadIdx.x;
    if (blockIdx.x == 0) {
        __shared__ int bad;
        if (threadIdx.x == 0) bad = 0;
        __syncthreads();
        const long long* q = (const long long*)eu;
        long long v = q[threadIdx.x];
        if (v < 0 || v >= N_NODES) bad = 1;
        __syncthreads();
        if (threadIdx.x == 0) d_is64 = bad ? 0 : 1;
    }
    // all-ones check over the full value array
    bool ok = true;
    for (int t = k; t < E_IN; t += gridDim.x * blockDim.x)
        if (ev[t] != 1.0f) ok = false;
    if (!ok) d_allones = 0;
}

__device__ __forceinline__ int get_idx(const void* __restrict__ p, int k) {
    if (d_is64) return (int)((const long long*)p)[k];
    return ((const int*)p)[k];
}

// degree/count accumulation; float atomics skipped when all values are 1.0
__global__ void deg_kernel(const void* __restrict__ eu,
                           const void* __restrict__ ei,
                           const float* __restrict__ ev) {
    int k = blockIdx.x * blockDim.x + threadIdx.x;
    if (k >= E_IN) return;
    int u  = get_idx(eu, k);
    int it = get_idx(ei, k);
    if ((unsigned)u >= U_NODES || (unsigned)it >= I_NODES) return;  // safety
    it += U_NODES;
    atomicAdd(&d_cnt[u], 1);
    atomicAdd(&d_cnt[it], 1);
    if (!d_allones) {
        float v = ev[k];
        atomicAdd(&d_deg[u], v);
        atomicAdd(&d_deg[it], v);
    }
}

// block-level exclusive scan of counts (+ fused dinv computation)
__global__ void scan1_kernel() {
    __shared__ int sh[SCAN_BLK];
    int t = threadIdx.x;
    int idx = blockIdx.x * SCAN_BLK + t;
    int v = (idx < N_NODES) ? d_cnt[idx] : 0;
    // fused dinv: deg == cnt when all values are 1.0 ((float)cnt exact < 2^24)
    if (idx < N_NODES) {
        float dg = d_allones ? (float)v : d_deg[idx];
        d_dinv[idx] = (dg > 0.0f) ? rsqrtf(fmaxf(dg, 1e-12f)) : 0.0f;
    }
    sh[t] = v;
    __syncthreads();
    for (int off = 1; off < SCAN_BLK; off <<= 1) {
        int x = (t >= off) ? sh[t - off] : 0;
        __syncthreads();
        sh[t] += x;
        __syncthreads();
    }
    if (idx < N_NODES) d_rowptr[idx] = sh[t] - v;   // block-local exclusive
    if (t == SCAN_BLK - 1) d_partials[blockIdx.x] = sh[t];
}

// parallel exclusive scan of the 147 block sums (one 256-thread block)
__global__ void scan2_kernel() {
    __shared__ int sh[256];
    int t = threadIdx.x;
    int v = (t < N_SCAN_BLOCKS) ? d_partials[t] : 0;
    sh[t] = v;
    __syncthreads();
    for (int off = 1; off < 256; off <<= 1) {
        int x = (t >= off) ? sh[t - off] : 0;
        __syncthreads();
        sh[t] += x;
        __syncthreads();
    }
    if (t < N_SCAN_BLOCKS) d_partials[t] = sh[t] - v;   // exclusive
}

__global__ void scan3_kernel() {
    int idx = blockIdx.x * blockDim.x + threadIdx.x;
    if (idx < N_NODES) {
        int rp = d_rowptr[idx] + d_partials[idx >> 10];
        d_rowptr[idx] = rp;
        d_wp[idx] = rp;
    }
    if (idx == 0) d_rowptr[N_NODES] = E_DIR;
}

__global__ void scatter_kernel(const void* __restrict__ eu,
                               const void* __restrict__ ei,
                               const float* __restrict__ ev) {
    int k = blockIdx.x * blockDim.x + threadIdx.x;
    if (k >= E_IN) return;
    int u  = get_idx(eu, k);
    int it = get_idx(ei, k);
    if ((unsigned)u >= U_NODES || (unsigned)it >= I_NODES) return;  // safety
    it += U_NODES;
    float v = d_allones ? 1.0f : ev[k];
    float w = d_dinv[u] * v * d_dinv[it];   // symmetric weight
    int p0 = atomicAdd(&d_wp[u], 1);
    d_col[p0] = it;
    d_w[p0]   = w;
    int p1 = atomicAdd(&d_wp[it], 1);
    d_col[p1] = u;
    d_w[p1]   = w;
}

// e0 = fp16(emb); acc = fp32(emb). float4 source loads (UH % 4 == 0).
__global__ void init_e_kernel(const float* __restrict__ emb_u,
                              const float* __restrict__ emb_i) {
    int q = blockIdx.x * blockDim.x + threadIdx.x;   // float4 index
    if (q >= NH / 4) return;
    int i = q * 4;
    float4 v = (i < UH) ? ((const float4*)emb_u)[q]
                        : ((const float4*)emb_i)[q - UH / 4];
    ((float4*)d_acc)[q] = v;
    __half2 h0 = __floats2half2_rn(v.x, v.y);
    __half2 h1 = __floats2half2_rn(v.z, v.w);
    uint2 p;
    p.x = *(unsigned int*)&h0;
    p.y = *(unsigned int*)&h1;
    ((uint2*)d_e0)[q] = p;
}

// ---------------- propagation layers ------------------------------------------
// Champion structure (split col/w scalar broadcasts, x4 unroll, fp32 acc RMW,
// LTB=64) with ONE change: e stored fp16 -> row gather is 128 B (4 sectors)
// instead of 256 B (8). Lane l loads one __half2 (dims 2l,2l+1), converts,
// accumulates in fp32.

__global__ void layer_kernel(int flip) {
    const __half* __restrict__ ein  = flip ? d_e1 : d_e0;
    __half*       __restrict__ eout = flip ? d_e0 : d_e1;
    int warp = (blockIdx.x * blockDim.x + threadIdx.x) >> 5;
    int lane = threadIdx.x & 31;
    if (warp >= N_NODES) return;
    int s = d_rowptr[warp];
    int e = d_rowptr[warp + 1];
    float2 sum = make_float2(0.0f, 0.0f);
    int base = lane * 2;
    int j = s;
    for (; j + 3 < e; j += 4) {          // unrolled x4 for MLP
        int   c0 = d_col[j],     c1 = d_col[j + 1];
        int   c2 = d_col[j + 2], c3 = d_col[j + 3];
        float w0 = d_w[j],       w1 = d_w[j + 1];
        float w2 = d_w[j + 2],   w3 = d_w[j + 3];
        __half2 h0 = *(const __half2*)(ein + (size_t)c0 * H + base);
        __half2 h1 = *(const __half2*)(ein + (size_t)c1 * H + base);
        __half2 h2 = *(const __half2*)(ein + (size_t)c2 * H + base);
        __half2 h3 = *(const __half2*)(ein + (size_t)c3 * H + base);
        float2 v0 = __half22float2(h0);
        float2 v1 = __half22float2(h1);
        float2 v2 = __half22float2(h2);
        float2 v3 = __half22float2(h3);
        sum.x += w0 * v0.x + w1 * v1.x + w2 * v2.x + w3 * v3.x;
        sum.y += w0 * v0.y + w1 * v1.y + w2 * v2.y + w3 * v3.y;
    }
    for (; j < e; j++) {
        int c = d_col[j];
        float w = d_w[j];
        float2 v = __half22float2(*(const __half2*)(ein + (size_t)c * H + base));
        sum.x += w * v.x;
        sum.y += w * v.y;
    }
    size_t o = (size_t)warp * H + base;
    *(__half2*)(eout + o) = __floats2half2_rn(sum.x, sum.y);
    float2* ap = (float2*)(d_acc + o);
    float2 a = *ap;
    a.x += sum.x;
    a.y += sum.y;
    *ap = a;
}

// ---------------- epilogue -----------------------------------------------------
// out = [acc_users/25 | emb_users | acc_items/25 | emb_items], float4 path.
__global__ void final_kernel(const float* __restrict__ emb_u,
                             const float* __restrict__ emb_i,
                             float* __restrict__ out, int out_n) {
    const float sc = 1.0f / 25.0f;   // alpha * 1/(L+1) = 1/5 * 1/5
    int q = blockIdx.x * blockDim.x + threadIdx.x;   // float4 index
    int i = q * 4;
    if (i >= out_n) return;
    if (i + 3 < out_n && i + 4 <= 2 * UH + 2 * IH) {
        float4 v;
        if (i < UH) {
            float4 a = ((const float4*)d_acc)[q];
            v = make_float4(a.x * sc, a.y * sc, a.z * sc, a.w * sc);
        } else if (i < 2 * UH) {
            v = ((const float4*)emb_u)[q - UH / 4];
        } else if (i < 2 * UH + IH) {
            float4 a = ((const float4*)d_acc)[UH / 4 + (q - 2 * UH / 4)];
            v = make_float4(a.x * sc, a.y * sc, a.z * sc, a.w * sc);
        } else {
            v = ((const float4*)emb_i)[q - (2 * UH + IH) / 4];
        }
        ((float4*)out)[q] = v;
    } else {
        for (int t = i; t < out_n && t < i + 4; t++) {
            float v;
            if (t < UH)                   v = d_acc[t] * sc;
            else if (t < 2 * UH)          v = emb_u[t - UH];
            else if (t < 2 * UH + IH)     v = d_acc[UH + (t - 2 * UH)] * sc;
            else if (t < 2 * UH + 2 * IH) v = emb_i[t - 2 * UH - IH];
            else                          v = 0.0f;
            out[t] = v;
        }
    }
}

// ---------------- launch ------------------------------------------------------

extern "C" void kernel_launch(void* const* d_in, const int* in_sizes, int n_in,
                              void* d_out, int out_size) {
    const float* emb_u = (const float*)d_in[0];
    const float* emb_i = (const float*)d_in[1];
    const void*  eu    = d_in[2];
    const void*  ei    = d_in[3];
    const float* ev    = (const float*)d_in[4];
    float* out = (float*)d_out;

    const int TB = 256;
    int gb_nodes = (N_NODES + TB - 1) / TB;
    int gb_edges = (E_IN + TB - 1) / TB;
    int gb_nh4   = (NH / 4 + TB - 1) / TB;
    int gb_out4  = (out_size / 4 + TB) / TB;

    zero_kernel<<<gb_nodes, TB>>>();          // also resets d_allones
    probe_kernel<<<592, TB>>>(eu, ev);        // dtype + all-ones (full scan)
    deg_kernel<<<gb_edges, TB>>>(eu, ei, ev);
    scan1_kernel<<<N_SCAN_BLOCKS, SCAN_BLK>>>();   // fused dinv
    scan2_kernel<<<1, 256>>>();
    scan3_kernel<<<gb_nodes, TB>>>();
    scatter_kernel<<<gb_edges, TB>>>(eu, ei, ev);
    init_e_kernel<<<gb_nh4, TB>>>(emb_u, emb_i);

    const int LTB = 64;                       // champion layer config
    int layer_blocks = (N_NODES * 32 + LTB - 1) / LTB;
    layer_kernel<<<layer_blocks, LTB>>>(0);   // e0 -> e1
    layer_kernel<<<layer_blocks, LTB>>>(1);   // e1 -> e0
    layer_kernel<<<layer_blocks, LTB>>>(0);   // e0 -> e1
    layer_kernel<<<layer_blocks, LTB>>>(1);   // e1 -> e0

    final_kernel<<<gb_out4, TB>>>(emb_u, emb_i, out, out_size);
}